// round 5
// baseline (speedup 1.0000x reference)
#include <cuda_runtime.h>
#include <cstdint>

// x: [N=64, C=512, H=56, W=56] fp32. 2:4 structured sparsity along C:
// within each group of 4 channels (same n,h,w), zero the 2 smallest-|x|
// entries (ties: lower channel index dropped first, matching jax top_k).
//
// R5: persistent grid-stride, single wave (148 SMs x 8 CTAs x 256 thr).
// Removes ~20 wave transitions + per-wave tail imbalance that left the
// DRAM pipe idle ~16% of the time in R1-R4 (all plateaued at 84% DRAM).

static constexpr int N_DIM  = 64;
static constexpr int C_DIM  = 512;
static constexpr int HW     = 56 * 56;          // 3136
static constexpr int HW4    = HW / 4;           // 784 float4 per channel plane
static constexpr int GROUPS = C_DIM / 4;        // 128
static constexpr int TOTAL_T = N_DIM * GROUPS * HW4; // 6,422,528 (fits int)

static constexpr int NUM_SMS   = 148;
static constexpr int CTAS_PER  = 8;
static constexpr int BLOCK     = 256;
static constexpr int GRID      = NUM_SMS * CTAS_PER;   // 1184 = one full wave
static constexpr int STRIDE    = GRID * BLOCK;         // 303,104

// keep element i iff at least 2 of the other 3 are "strictly smaller"
// under less(j,i) = (|a_j| < |a_i|) || (|a_j| == |a_i| && j < i).
__device__ __forceinline__ void mask4(float& x0, float& x1, float& x2, float& x3) {
    float a0 = fabsf(x0), a1 = fabsf(x1), a2 = fabsf(x2), a3 = fabsf(x3);
    int r0 = 0, r1 = 0, r2 = 0, r3 = 0;
    if (a0 <= a1) r1++; else r0++;   // less(0,1)=a0<=a1 ; less(1,0)=a1<a0
    if (a0 <= a2) r2++; else r0++;
    if (a0 <= a3) r3++; else r0++;
    if (a1 <= a2) r2++; else r1++;
    if (a1 <= a3) r3++; else r1++;
    if (a2 <= a3) r3++; else r2++;
    x0 = (r0 >= 2) ? x0 : 0.0f;
    x1 = (r1 >= 2) ? x1 : 0.0f;
    x2 = (r2 >= 2) ? x2 : 0.0f;
    x3 = (r3 >= 2) ? x3 : 0.0f;
}

__global__ void __launch_bounds__(BLOCK, CTAS_PER)
sparsity24_kernel(const float4* __restrict__ x4, float4* __restrict__ o4) {
    int t = blockIdx.x * BLOCK + threadIdx.x;

    #pragma unroll 1
    for (; t < TOTAL_T; t += STRIDE) {
        // decode: t -> (ng, hw4); constant divisor -> mul-shift in SASS
        int hw4 = t % HW4;
        int ng  = t / HW4;
        int base = ng * (4 * HW4) + hw4;   // max 25,690,112 < 2^31

        float4 v0 = x4[base];
        float4 v1 = x4[base + HW4];
        float4 v2 = x4[base + 2 * HW4];
        float4 v3 = x4[base + 3 * HW4];

        mask4(v0.x, v1.x, v2.x, v3.x);
        mask4(v0.y, v1.y, v2.y, v3.y);
        mask4(v0.z, v1.z, v2.z, v3.z);
        mask4(v0.w, v1.w, v2.w, v3.w);

        __stcs(&o4[base],           v0);
        __stcs(&o4[base + HW4],     v1);
        __stcs(&o4[base + 2 * HW4], v2);
        __stcs(&o4[base + 3 * HW4], v3);
    }
}

extern "C" void kernel_launch(void* const* d_in, const int* in_sizes, int n_in,
                              void* d_out, int out_size) {
    const float4* x4 = (const float4*)d_in[0];
    float4* o4 = (float4*)d_out;
    sparsity24_kernel<<<GRID, BLOCK>>>(x4, o4);
}

// round 6
// speedup vs baseline: 1.1590x; 1.1590x over previous
#include <cuda_runtime.h>
#include <cstdint>

// x: [N=64, C=512, H=56, W=56] fp32. 2:4 structured sparsity along C:
// within each group of 4 channels (same n,h,w), zero the 2 smallest-|x|
// entries (ties: lower channel index dropped first, matching jax top_k).
//
// R6 = best-of-all-rounds combination:
//  - R1 structure: 4 float4 loads/thread, one hw4 column per thread
//  - R1 cache policy: PLAIN loads and PLAIN stores (measured best DRAM%=85.0;
//    .cs variants measured 83.9-84.2%)
//  - R4 addressing: 32-bit index math (max float4 index 25.7M < 2^31),
//    __launch_bounds__(256,8) pinning regs<=32
// Evidence from R2 (MLP=8 -> regs 60, occ 40%, regress) and R5 (persistent
// grid-stride serializes load batches, regress): fresh-CTA, MLP=4,
// high-occupancy launch is optimal. This op is at the HBM r+w ceiling
// (~6.7 TB/s = 84-85% of 8 TB/s spec).

static constexpr int HW4    = (56 * 56) / 4;    // 784 float4 per channel plane
static constexpr int TOTAL_T = 64 * 128 * HW4;  // 6,422,528 (fits int)

// keep element i iff at least 2 of the other 3 are "strictly smaller"
// under less(j,i) = (|a_j| < |a_i|) || (|a_j| == |a_i| && j < i).
__device__ __forceinline__ void mask4(float& x0, float& x1, float& x2, float& x3) {
    float a0 = fabsf(x0), a1 = fabsf(x1), a2 = fabsf(x2), a3 = fabsf(x3);
    int r0 = 0, r1 = 0, r2 = 0, r3 = 0;
    if (a0 <= a1) r1++; else r0++;   // less(0,1)=a0<=a1 ; less(1,0)=a1<a0
    if (a0 <= a2) r2++; else r0++;
    if (a0 <= a3) r3++; else r0++;
    if (a1 <= a2) r2++; else r1++;
    if (a1 <= a3) r3++; else r1++;
    if (a2 <= a3) r3++; else r2++;
    x0 = (r0 >= 2) ? x0 : 0.0f;
    x1 = (r1 >= 2) ? x1 : 0.0f;
    x2 = (r2 >= 2) ? x2 : 0.0f;
    x3 = (r3 >= 2) ? x3 : 0.0f;
}

__global__ void __launch_bounds__(256, 8)
sparsity24_kernel(const float4* __restrict__ x4, float4* __restrict__ o4) {
    int t = blockIdx.x * 256 + threadIdx.x;
    if (t >= TOTAL_T) return;

    // decode: t -> (ng, hw4); constant divisor -> mul-shift in SASS
    int hw4 = t % HW4;
    int ng  = t / HW4;
    int base = ng * (4 * HW4) + hw4;   // max 25,690,112 < 2^31

    float4 v0 = x4[base];
    float4 v1 = x4[base + HW4];
    float4 v2 = x4[base + 2 * HW4];
    float4 v3 = x4[base + 3 * HW4];

    mask4(v0.x, v1.x, v2.x, v3.x);
    mask4(v0.y, v1.y, v2.y, v3.y);
    mask4(v0.z, v1.z, v2.z, v3.z);
    mask4(v0.w, v1.w, v2.w, v3.w);

    o4[base]           = v0;
    o4[base + HW4]     = v1;
    o4[base + 2 * HW4] = v2;
    o4[base + 3 * HW4] = v3;
}

extern "C" void kernel_launch(void* const* d_in, const int* in_sizes, int n_in,
                              void* d_out, int out_size) {
    const float4* x4 = (const float4*)d_in[0];
    float4* o4 = (float4*)d_out;
    int blocks = (TOTAL_T + 255) / 256;
    sparsity24_kernel<<<blocks, 256>>>(x4, o4);
}

// round 7
// speedup vs baseline: 1.1651x; 1.0053x over previous
#include <cuda_runtime.h>
#include <cstdint>

// x: [N=64, C=512, H=56, W=56] fp32. 2:4 structured sparsity along C:
// within each group of 4 channels (same n,h,w), zero the 2 smallest-|x|
// entries (ties: lower channel index dropped first, matching jax top_k).
//
// R7 = R6 + write-through stores (__stwt). Output is never re-read;
// .wt skips L2 write-allocate entirely, freeing LTS bandwidth/capacity
// for the inbound read stream. All other choices are the measured-best
// R6 baseline: 4 float4 loads/thread (MLP=4), plain loads, 32-bit index
// math, __launch_bounds__(256,8) -> regs=32, occ~80%.
//
// Session evidence: R1/R3/R4/R6 all in 121.4-122.0us (noise band) at
// 6.6-6.7 TB/s = 84-85% of spec, the B300 streaming ceiling. R2 (MLP=8,
// occ 40%) and R5 (persistent grid-stride) regressed.

static constexpr int HW4     = (56 * 56) / 4;   // 784 float4 per channel plane
static constexpr int TOTAL_T = 64 * 128 * HW4;  // 6,422,528 (fits int)

// keep element i iff at least 2 of the other 3 are "strictly smaller"
// under less(j,i) = (|a_j| < |a_i|) || (|a_j| == |a_i| && j < i).
__device__ __forceinline__ void mask4(float& x0, float& x1, float& x2, float& x3) {
    float a0 = fabsf(x0), a1 = fabsf(x1), a2 = fabsf(x2), a3 = fabsf(x3);
    int r0 = 0, r1 = 0, r2 = 0, r3 = 0;
    if (a0 <= a1) r1++; else r0++;   // less(0,1)=a0<=a1 ; less(1,0)=a1<a0
    if (a0 <= a2) r2++; else r0++;
    if (a0 <= a3) r3++; else r0++;
    if (a1 <= a2) r2++; else r1++;
    if (a1 <= a3) r3++; else r1++;
    if (a2 <= a3) r3++; else r2++;
    x0 = (r0 >= 2) ? x0 : 0.0f;
    x1 = (r1 >= 2) ? x1 : 0.0f;
    x2 = (r2 >= 2) ? x2 : 0.0f;
    x3 = (r3 >= 2) ? x3 : 0.0f;
}

__global__ void __launch_bounds__(256, 8)
sparsity24_kernel(const float4* __restrict__ x4, float4* __restrict__ o4) {
    int t = blockIdx.x * 256 + threadIdx.x;
    if (t >= TOTAL_T) return;

    // decode: t -> (ng, hw4); constant divisor -> mul-shift in SASS
    int hw4 = t % HW4;
    int ng  = t / HW4;
    int base = ng * (4 * HW4) + hw4;   // max 25,690,112 < 2^31

    float4 v0 = x4[base];
    float4 v1 = x4[base + HW4];
    float4 v2 = x4[base + 2 * HW4];
    float4 v3 = x4[base + 3 * HW4];

    mask4(v0.x, v1.x, v2.x, v3.x);
    mask4(v0.y, v1.y, v2.y, v3.y);
    mask4(v0.z, v1.z, v2.z, v3.z);
    mask4(v0.w, v1.w, v2.w, v3.w);

    __stwt(&o4[base],           v0);
    __stwt(&o4[base + HW4],     v1);
    __stwt(&o4[base + 2 * HW4], v2);
    __stwt(&o4[base + 3 * HW4], v3);
}

extern "C" void kernel_launch(void* const* d_in, const int* in_sizes, int n_in,
                              void* d_out, int out_size) {
    const float4* x4 = (const float4*)d_in[0];
    float4* o4 = (float4*)d_out;
    int blocks = (TOTAL_T + 255) / 256;
    sparsity24_kernel<<<blocks, 256>>>(x4, o4);
}